// round 1
// baseline (speedup 1.0000x reference)
#include <cuda_runtime.h>
#include <float.h>

// ROI max pooling, NHWC fp32.
// feat: [B=8, H=50, W=50, C=256], rois: [N,5] (img, x1, y1, x2, y2) inclusive.
// out: [N, PH=7, PW=7, C=256].
//
// Bin partition matches reference: row_bin = min(dy*PH // roi_h, PH-1).
// Inverse: bin i covers dy in [ceil(i*roi_h/PH), ceil((i+1)*roi_h/PH)) for
// i < PH-1, and [ceil((PH-1)*roi_h/PH), roi_h) for the last bin.

#define PH 7
#define PW 7
#define CCH 256
#define FH 50
#define FW 50

__global__ __launch_bounds__(64, 32)
void roi_pool_kernel(const float* __restrict__ feat,
                     const int*   __restrict__ rois,
                     float*       __restrict__ out)
{
    const int bin  = blockIdx.x;            // roi*49 + br*7 + bc
    const int roi  = bin / (PH * PW);
    const int b    = bin - roi * (PH * PW);
    const int br   = b / PW;
    const int bc   = b - br * PW;

    const int* r = rois + roi * 5;
    const int img = r[0];
    const int x1  = r[1];
    const int y1  = r[2];
    const int x2  = r[3];
    const int y2  = r[4];
    const int roi_h = y2 - y1 + 1;
    const int roi_w = x2 - x1 + 1;

    // pixel range (relative to roi origin) for this bin
    const int rs = (br * roi_h + PH - 1) / PH;
    const int re = (br == PH - 1) ? roi_h : ((br + 1) * roi_h + PH - 1) / PH;
    const int cs = (bc * roi_w + PW - 1) / PW;
    const int ce = (bc == PW - 1) ? roi_w : ((bc + 1) * roi_w + PW - 1) / PW;

    const int t = threadIdx.x;              // 0..63, each owns 4 channels
    const int coff = t * 4;

    float4 m = make_float4(-FLT_MAX, -FLT_MAX, -FLT_MAX, -FLT_MAX);

    // base pointer for (img, y1, x1, coff)
    const float* base = feat
        + (((size_t)img * FH + (size_t)y1) * FW + (size_t)x1) * CCH
        + coff;

    for (int y = rs; y < re; ++y) {
        const float* rowp = base + (size_t)y * (FW * CCH);
        #pragma unroll 4
        for (int x = cs; x < ce; ++x) {
            const float4 v = *reinterpret_cast<const float4*>(rowp + (size_t)x * CCH);
            m.x = fmaxf(m.x, v.x);
            m.y = fmaxf(m.y, v.y);
            m.z = fmaxf(m.z, v.z);
            m.w = fmaxf(m.w, v.w);
        }
    }

    float4* o = reinterpret_cast<float4*>(out + (size_t)bin * CCH + coff);
    *o = m;
}

extern "C" void kernel_launch(void* const* d_in, const int* in_sizes, int n_in,
                              void* d_out, int out_size)
{
    const float* feat = (const float*)d_in[0];
    const int*   rois = (const int*)d_in[1];
    // pool_height / pool_width (d_in[2], d_in[3]) are fixed at 7 for this
    // problem; grid shape must be static for graph capture.
    const int n_rois = in_sizes[1] / 5;
    float* out = (float*)d_out;

    const int blocks = n_rois * PH * PW;
    roi_pool_kernel<<<blocks, 64>>>(feat, rois, out);
}